// round 4
// baseline (speedup 1.0000x reference)
#include <cuda_runtime.h>

// Problem constants (fixed by setup_inputs)
#define CC      4
#define HH      256
#define WW      256
#define EE      32
#define OO      32
#define NN      125                  // (256-7)/2+1
#define NQ      (NN * NN)            // 15625
#define NQP     15648                // NQ padded to multiple of 32
#define DP      224                  // padded patch: 28 rows x 8 floats (7 used)
#define DIST_SCALE 10.0f
#define W_THR   1e-7f
#define FULL    0xFFFFFFFFu

__device__ float g_XP[NQ * DP];      // unfolded padded patches  (~13.7MB)
__device__ float g_ZT[DP * NQP];     // transposed aggregation   (~14.0MB)

// ---------------------------------------------------------------------------
// K0: warp-per-query unfold. Patch row (c,r) = 8 floats x[c, 2i+r, 2j .. 2j+7]
// (8th float is padding data, never read downstream). 112 float2 slots/query.
// ---------------------------------------------------------------------------
__global__ __launch_bounds__(256) void unfold_kernel(const float* __restrict__ x) {
    const int lane = threadIdx.x & 31;
    const int wrp  = threadIdx.x >> 5;
    const int q    = blockIdx.x * 8 + wrp;
    if (q >= NQ) return;

    const int i = q / NN;
    const int j = q - i * NN;
    const float* src0 = x + (2 * i) * WW + 2 * j;   // + c*65536 + r*256
    float* dst = g_XP + q * DP;

#pragma unroll
    for (int k = 0; k < 4; k++) {
        const int slot = k * 32 + lane;             // float2 slot
        if (slot < 112) {
            const int row  = slot >> 2;             // 0..27
            const int pair = slot & 3;
            const int c = row / 7;
            const int r = row - c * 7;
            const float2 v = *reinterpret_cast<const float2*>(
                src0 + c * (HH * WW) + r * WW + pair * 2);
            *reinterpret_cast<float2*>(dst + slot * 2) = v;
        }
    }
}

// ---------------------------------------------------------------------------
// K1: warp = query (4 queries/warp, 32/CTA).
//  p1: coalesced distances (8 lanes per candidate row, 4 candidates/LDG.128)
//  p2: warp softmax + ballot threshold
//  p3: survivor gather from XP (7 contiguous lines: 2x LD.128 per lane)
//  p4: CTA-cooperative transposed store (full 128B lines, 32 q per d)
// ---------------------------------------------------------------------------
__global__ __launch_bounds__(256) void agg_kernel(const float* __restrict__ xe,
                                                  const float* __restrict__ ye,
                                                  const int*   __restrict__ inds) {
    const int lane = threadIdx.x & 31;
    const int wrp  = threadIdx.x >> 5;
    const int q0   = blockIdx.x * 32;

    __shared__ float s_z [32][225];   // 225 -> conflict-free transpose reads
    __shared__ float s_d2[8][OO];

#pragma unroll 1
    for (int k4 = 0; k4 < 4; k4++) {
        const int q  = q0 + wrp * 4 + k4;
        if (q >= NQ) break;                       // warp-uniform
        const int ql = wrp * 4 + k4;

        // ---- p1: distances ----
        const int g  = lane >> 3;
        const int ch = lane & 7;
        const float4 y4 = reinterpret_cast<const float4*>(ye + q * EE)[ch];
        const int p_l   = inds[q * OO + lane];

        float acck[8];
#pragma unroll
        for (int k = 0; k < 8; k++) {
            const int po = __shfl_sync(FULL, p_l, k * 4 + g);
            const float4 v = reinterpret_cast<const float4*>(xe + po * EE)[ch];
            const float dx = v.x - y4.x, dy = v.y - y4.y;
            const float dz = v.z - y4.z, dw = v.w - y4.w;
            acck[k] = dx * dx + dy * dy + dz * dz + dw * dw;
        }
#pragma unroll
        for (int k = 0; k < 8; k++) {
            acck[k] += __shfl_xor_sync(FULL, acck[k], 1);
            acck[k] += __shfl_xor_sync(FULL, acck[k], 2);
            acck[k] += __shfl_xor_sync(FULL, acck[k], 4);
        }
        if (ch == 0) {
#pragma unroll
            for (int k = 0; k < 8; k++) s_d2[wrp][k * 4 + g] = acck[k];
        }
        __syncwarp();
        const float d2 = s_d2[wrp][lane];
        __syncwarp();

        // ---- p2: softmax + threshold ----
        float m = d2;
#pragma unroll
        for (int off = 16; off; off >>= 1)
            m = fminf(m, __shfl_xor_sync(FULL, m, off));
        const float ev = __expf(-DIST_SCALE * (d2 - m));
        float sum = ev;
#pragma unroll
        for (int off = 16; off; off >>= 1)
            sum += __shfl_xor_sync(FULL, sum, off);
        const float w = ev / sum;

        const unsigned surv = __ballot_sync(FULL, w >= W_THR);
        const int ks = __popc(surv);

        // ---- p3: survivor gathers from XP ----
        float4 a0 = make_float4(0.f, 0.f, 0.f, 0.f);
        float4 a1 = make_float4(0.f, 0.f, 0.f, 0.f);
        for (int s = 0; s < ks; s++) {
            const int   lo = __fns(surv, 0, s + 1);
            const float ws = __shfl_sync(FULL, w,   lo);
            const int   po = __shfl_sync(FULL, p_l, lo);
            const float4* P = reinterpret_cast<const float4*>(g_XP + po * DP);
            const float4 v0 = P[lane];                     // floats 0..127
            a0.x += ws * v0.x; a0.y += ws * v0.y;
            a0.z += ws * v0.z; a0.w += ws * v0.w;
            if (lane < 24) {                               // floats 128..223
                const float4 v1 = P[32 + lane];
                a1.x += ws * v1.x; a1.y += ws * v1.y;
                a1.z += ws * v1.z; a1.w += ws * v1.w;
            }
        }
        {
            const int b = lane * 4;
            s_z[ql][b + 0] = a0.x; s_z[ql][b + 1] = a0.y;
            s_z[ql][b + 2] = a0.z; s_z[ql][b + 3] = a0.w;
        }
        if (lane < 24) {
            const int b = 128 + lane * 4;
            s_z[ql][b + 0] = a1.x; s_z[ql][b + 1] = a1.y;
            s_z[ql][b + 2] = a1.z; s_z[ql][b + 3] = a1.w;
        }
        __syncwarp();
    }

    __syncthreads();

    // ---- p4: zT[d][q0..q0+31] stores (coalesced; overflow lands in q-pad) ----
#pragma unroll
    for (int mIdx = threadIdx.x; mIdx < DP * 32; mIdx += 256) {
        const int d  = mIdx >> 5;
        const int qq = mIdx & 31;
        g_ZT[d * NQP + q0 + qq] = s_z[qq][d];
    }
}

// ---------------------------------------------------------------------------
// K2: fold via smem staging. CTA = one (c,h) output row. Each zT element is
// needed by exactly one output pixel; stage the <=28 relevant 125-long rows
// coalesced, then each thread sums <=16 LDS values. Writes every element.
// ---------------------------------------------------------------------------
__global__ __launch_bounds__(256) void fold_kernel(float* __restrict__ out) {
    const int c = blockIdx.x >> 8;
    const int h = blockIdx.x & 255;
    const int par = h & 1;

    __shared__ float s_rows[28][126];

    for (int mIdx = threadIdx.x; mIdx < 28 * 125; mIdx += 256) {
        const int rr = mIdx / 125;
        const int t  = mIdx - rr * 125;
        const int ridx = rr / 7;
        const int s    = rr - ridx * 7;
        const int r    = par + 2 * ridx;         // may be 7 (invalid)
        const int i2   = h - r;
        float v = 0.f;
        if (r <= 6 && i2 >= 0 && i2 <= 2 * (NN - 1)) {
            const int i = i2 >> 1;
            const int d = (c * 7 + r) * 8 + s;
            v = g_ZT[d * NQP + i * NN + t];
        }
        s_rows[rr][t] = v;
    }
    __syncthreads();

    const int w = threadIdx.x;
    const int wpar = w & 1;
    float acc = 0.f;
#pragma unroll
    for (int ridx = 0; ridx < 4; ridx++) {
#pragma unroll
        for (int si = 0; si < 4; si++) {
            const int s = wpar + 2 * si;
            if (s > 6) continue;
            const int j2 = w - s;
            if (j2 >= 0 && j2 <= 2 * (NN - 1))
                acc += s_rows[ridx * 7 + s][j2 >> 1];
        }
    }
    out[blockIdx.x * 256 + w] = acc;
}

// ---------------------------------------------------------------------------
extern "C" void kernel_launch(void* const* d_in, const int* in_sizes, int n_in,
                              void* d_out, int out_size) {
    const float* x    = (const float*)d_in[0];
    const float* xe   = (const float*)d_in[1];
    const float* ye   = (const float*)d_in[2];
    const int*   inds = (const int*)  d_in[3];
    float*       out  = (float*)d_out;
    (void)in_sizes; (void)n_in; (void)out_size;

    unfold_kernel<<<(NQ + 7) / 8, 256>>>(x);
    agg_kernel<<<(NQ + 31) / 32, 256>>>(xe, ye, inds);
    fold_kernel<<<CC * HH, 256>>>(out);
}

// round 6
// speedup vs baseline: 1.2305x; 1.2305x over previous
#include <cuda_runtime.h>

// Problem constants (fixed by setup_inputs)
#define CC      4
#define HH      256
#define WW      256
#define EE      32
#define OO      32
#define NN      125                  // (256-7)/2+1
#define NQ      (NN * NN)            // 15625
#define NQS     15632                // zT q-stride: mult of 8 -> 32B-aligned rows
#define DD      196                  // C*7*7 ; d = (c*7+r)*7 + s = row*7 + s
#define DIST_SCALE 10.0f
#define W_THR   1e-7f
#define FULL    0xFFFFFFFFu

__device__ float g_ZT[DD * NQS];     // transposed aggregation zT[d][q] (~12.3MB)

// ---------------------------------------------------------------------------
// K1: one query per warp, 8 warps/CTA (grid 1954 -> 13 waves of latency hiding)
//  p1: coalesced distances: 8 lanes per candidate row, 4 candidates per LDG.128
//  p2: warp softmax + ballot threshold (deterministic)
//  p3: survivor gather DIRECT from x, row-grouped: 4 LDG.64/survivor, each
//      instr = 8 whole patch rows x 4 lanes (32B/row) -> ~9 lines/instr
//  p4: CTA-cooperative transposed store zT[d][q0..q0+7] (32B sectors)
// ---------------------------------------------------------------------------
__global__ __launch_bounds__(256) void agg_kernel(const float* __restrict__ x,
                                                  const float* __restrict__ xe,
                                                  const float* __restrict__ ye,
                                                  const int*   __restrict__ inds) {
    const int lane = threadIdx.x & 31;
    const int wrp  = threadIdx.x >> 5;
    const int q0   = blockIdx.x * 8;
    const int q    = q0 + wrp;

    __shared__ float s_z [8][DD];
    __shared__ float s_d2[8][OO];

    if (q < NQ) {                                  // warp-uniform
        // ---- p1: distances ----
        const int g  = lane >> 3;                  // candidate group in instr
        const int ch = lane & 7;                   // float4 chunk of row
        const float4 y4 = reinterpret_cast<const float4*>(ye + q * EE)[ch];
        const int p_l   = inds[q * OO + lane];

        float acck[8];
#pragma unroll
        for (int k = 0; k < 8; k++) {
            const int po = __shfl_sync(FULL, p_l, k * 4 + g);
            const float4 v = reinterpret_cast<const float4*>(xe + po * EE)[ch];
            const float dx = v.x - y4.x, dy = v.y - y4.y;
            const float dz = v.z - y4.z, dw = v.w - y4.w;
            acck[k] = dx * dx + dy * dy + dz * dz + dw * dw;
        }
#pragma unroll
        for (int k = 0; k < 8; k++) {
            acck[k] += __shfl_xor_sync(FULL, acck[k], 1);
            acck[k] += __shfl_xor_sync(FULL, acck[k], 2);
            acck[k] += __shfl_xor_sync(FULL, acck[k], 4);
        }
        if (ch == 0) {
#pragma unroll
            for (int k = 0; k < 8; k++) s_d2[wrp][k * 4 + g] = acck[k];
        }
        __syncwarp();
        const float d2 = s_d2[wrp][lane];

        // ---- p2: softmax + threshold ----
        float m = d2;
#pragma unroll
        for (int off = 16; off; off >>= 1)
            m = fminf(m, __shfl_xor_sync(FULL, m, off));
        const float ev = __expf(-DIST_SCALE * (d2 - m));
        float sum = ev;
#pragma unroll
        for (int off = 16; off; off >>= 1)
            sum += __shfl_xor_sync(FULL, sum, off);
        const float w = ev / sum;

        const unsigned surv = __ballot_sync(FULL, w >= W_THR);
        const int ks = __popc(surv);

        // ---- p3: row-grouped survivor gather from x ----
        // instr t covers rows t*8 + (lane>>2); pair = lane&3 -> floats 2p,2p+1
        const int row3 = lane >> 2;
        const int pair = lane & 3;
        int  offs[4];
        bool act [4];
        int  drow[4];
#pragma unroll
        for (int t = 0; t < 4; t++) {
            const int row = t * 8 + row3;          // 0..31 (28..31 inactive)
            act[t]  = (row < 28);
            const int rc = act[t] ? row : 0;
            const int c  = rc / 7;
            const int r  = rc - c * 7;
            offs[t] = c * (HH * WW) + r * WW + pair * 2;
            drow[t] = rc * 7;                      // d base for this row
        }

        float2 acc[4];
#pragma unroll
        for (int t = 0; t < 4; t++) acc[t] = make_float2(0.f, 0.f);

        for (int s = 0; s < ks; s++) {
            const int   lo = __fns(surv, 0, s + 1);
            const float ws = __shfl_sync(FULL, w,   lo);
            const int   po = __shfl_sync(FULL, p_l, lo);
            const int   pi = po / NN;
            const int   pj = po - pi * NN;
            const int   pb = pi * (2 * WW) + pj * 2;   // 8B-aligned
#pragma unroll
            for (int t = 0; t < 4; t++) {
                if (act[t]) {
                    const float2 v = *reinterpret_cast<const float2*>(
                        x + offs[t] + pb);             // reads s=2p,2p+1 (s=7 pad ok)
                    acc[t].x += ws * v.x;
                    acc[t].y += ws * v.y;
                }
            }
        }

#pragma unroll
        for (int t = 0; t < 4; t++) {
            if (act[t]) {
                const int d0 = drow[t] + pair * 2;
                s_z[wrp][d0] = acc[t].x;
                if (pair < 3) s_z[wrp][d0 + 1] = acc[t].y;   // s=7 discarded
            }
        }
    }

    __syncthreads();

    // ---- p4: transposed store zT[d][q0+qq] ----
#pragma unroll
    for (int mIdx = threadIdx.x; mIdx < DD * 8; mIdx += 256) {
        const int d  = mIdx >> 3;
        const int qq = mIdx & 7;
        if (q0 + qq < NQ)
            g_ZT[d * NQS + q0 + qq] = s_z[qq][d];
    }
}

// ---------------------------------------------------------------------------
// K2: fold via smem staging. CTA = one (c,h) output row. Stage the <=28
// relevant zT rows (each element used by exactly one pixel) coalesced, then
// each thread sums <=16 LDS values. Writes every output element (poison-safe).
// ---------------------------------------------------------------------------
__global__ __launch_bounds__(256) void fold_kernel(float* __restrict__ out) {
    const int c   = blockIdx.x >> 8;
    const int h   = blockIdx.x & 255;
    const int par = h & 1;

    __shared__ float s_rows[28][126];   // [ridx*7+s][j] ; 126 pad

    for (int mIdx = threadIdx.x; mIdx < 28 * 125; mIdx += 256) {
        const int rr = mIdx / 125;
        const int t  = mIdx - rr * 125;
        const int ridx = rr / 7;
        const int s    = rr - ridx * 7;
        const int r    = par + 2 * ridx;          // may be 7 (invalid, par=1)
        const int i2   = h - r;
        float v = 0.f;
        if (r <= 6 && i2 >= 0 && i2 <= 2 * (NN - 1)) {
            const int i = i2 >> 1;
            const int d = (c * 7 + r) * 7 + s;
            v = g_ZT[d * NQS + i * NN + t];
        }
        s_rows[rr][t] = v;
    }
    __syncthreads();

    const int w    = threadIdx.x;
    const int wpar = w & 1;
    float acc = 0.f;
#pragma unroll
    for (int ridx = 0; ridx < 4; ridx++) {
#pragma unroll
        for (int si = 0; si < 4; si++) {
            const int s = wpar + 2 * si;
            if (s > 6) continue;
            const int j2 = w - s;
            if (j2 >= 0 && j2 <= 2 * (NN - 1))
                acc += s_rows[ridx * 7 + s][j2 >> 1];
        }
    }
    out[blockIdx.x * 256 + w] = acc;
}

// ---------------------------------------------------------------------------
extern "C" void kernel_launch(void* const* d_in, const int* in_sizes, int n_in,
                              void* d_out, int out_size) {
    const float* x    = (const float*)d_in[0];
    const float* xe   = (const float*)d_in[1];
    const float* ye   = (const float*)d_in[2];
    const int*   inds = (const int*)  d_in[3];
    float*       out  = (float*)d_out;
    (void)in_sizes; (void)n_in; (void)out_size;

    agg_kernel<<<(NQ + 7) / 8, 256>>>(x, xe, ye, inds);
    fold_kernel<<<CC * HH, 256>>>(out);
}

// round 7
// speedup vs baseline: 1.3416x; 1.0903x over previous
#include <cuda_runtime.h>

// Problem constants (fixed by setup_inputs)
#define CC      4
#define HH      256
#define WW      256
#define EE      32
#define OO      32
#define NN      125                  // (256-7)/2+1
#define NQ      (NN * NN)            // 15625
#define NQS     15632                // zT q-stride: mult of 8 -> 32B-aligned rows
#define DD      196                  // C*7*7 ; d = (c*7+r)*7 + s = row*7 + s
#define DIST_SCALE 10.0f
#define W_THR   1e-7f
#define FULL    0xFFFFFFFFu

__device__ float g_ZT[DD * NQS];     // transposed aggregation zT[d][q] (~12.3MB)

// ---------------------------------------------------------------------------
// K1: one query per warp, 8 warps/CTA (unchanged from round 6 - measured 14.5us)
// ---------------------------------------------------------------------------
__global__ __launch_bounds__(256) void agg_kernel(const float* __restrict__ x,
                                                  const float* __restrict__ xe,
                                                  const float* __restrict__ ye,
                                                  const int*   __restrict__ inds) {
    const int lane = threadIdx.x & 31;
    const int wrp  = threadIdx.x >> 5;
    const int q0   = blockIdx.x * 8;
    const int q    = q0 + wrp;

    __shared__ float s_z [8][DD];
    __shared__ float s_d2[8][OO];

    if (q < NQ) {                                  // warp-uniform
        // ---- p1: distances ----
        const int g  = lane >> 3;
        const int ch = lane & 7;
        const float4 y4 = reinterpret_cast<const float4*>(ye + q * EE)[ch];
        const int p_l   = inds[q * OO + lane];

        float acck[8];
#pragma unroll
        for (int k = 0; k < 8; k++) {
            const int po = __shfl_sync(FULL, p_l, k * 4 + g);
            const float4 v = reinterpret_cast<const float4*>(xe + po * EE)[ch];
            const float dx = v.x - y4.x, dy = v.y - y4.y;
            const float dz = v.z - y4.z, dw = v.w - y4.w;
            acck[k] = dx * dx + dy * dy + dz * dz + dw * dw;
        }
#pragma unroll
        for (int k = 0; k < 8; k++) {
            acck[k] += __shfl_xor_sync(FULL, acck[k], 1);
            acck[k] += __shfl_xor_sync(FULL, acck[k], 2);
            acck[k] += __shfl_xor_sync(FULL, acck[k], 4);
        }
        if (ch == 0) {
#pragma unroll
            for (int k = 0; k < 8; k++) s_d2[wrp][k * 4 + g] = acck[k];
        }
        __syncwarp();
        const float d2 = s_d2[wrp][lane];

        // ---- p2: softmax + threshold ----
        float m = d2;
#pragma unroll
        for (int off = 16; off; off >>= 1)
            m = fminf(m, __shfl_xor_sync(FULL, m, off));
        const float ev = __expf(-DIST_SCALE * (d2 - m));
        float sum = ev;
#pragma unroll
        for (int off = 16; off; off >>= 1)
            sum += __shfl_xor_sync(FULL, sum, off);
        const float w = ev / sum;

        const unsigned surv = __ballot_sync(FULL, w >= W_THR);
        const int ks = __popc(surv);

        // ---- p3: row-grouped survivor gather from x ----
        const int row3 = lane >> 2;
        const int pair = lane & 3;
        int  offs[4];
        bool act [4];
        int  drow[4];
#pragma unroll
        for (int t = 0; t < 4; t++) {
            const int row = t * 8 + row3;
            act[t]  = (row < 28);
            const int rc = act[t] ? row : 0;
            const int c  = rc / 7;
            const int r  = rc - c * 7;
            offs[t] = c * (HH * WW) + r * WW + pair * 2;
            drow[t] = rc * 7;
        }

        float2 acc[4];
#pragma unroll
        for (int t = 0; t < 4; t++) acc[t] = make_float2(0.f, 0.f);

        for (int s = 0; s < ks; s++) {
            const int   lo = __fns(surv, 0, s + 1);
            const float ws = __shfl_sync(FULL, w,   lo);
            const int   po = __shfl_sync(FULL, p_l, lo);
            const int   pi = po / NN;
            const int   pj = po - pi * NN;
            const int   pb = pi * (2 * WW) + pj * 2;
#pragma unroll
            for (int t = 0; t < 4; t++) {
                if (act[t]) {
                    const float2 v = *reinterpret_cast<const float2*>(
                        x + offs[t] + pb);
                    acc[t].x += ws * v.x;
                    acc[t].y += ws * v.y;
                }
            }
        }

#pragma unroll
        for (int t = 0; t < 4; t++) {
            if (act[t]) {
                const int d0 = drow[t] + pair * 2;
                s_z[wrp][d0] = acc[t].x;
                if (pair < 3) s_z[wrp][d0 + 1] = acc[t].y;
            }
        }
    }

    __syncthreads();

    // ---- p4: transposed store zT[d][q0+qq] ----
#pragma unroll
    for (int mIdx = threadIdx.x; mIdx < DD * 8; mIdx += 256) {
        const int d  = mIdx >> 3;
        const int qq = mIdx & 7;
        if (q0 + qq < NQ)
            g_ZT[d * NQS + q0 + qq] = s_z[qq][d];
    }
}

// ---------------------------------------------------------------------------
// K2: fold, instruction-minimized.
//  Staging: warp<->row assignment (no division), 4 coalesced LDG.32 per lane.
//  Sum: 16 LDS at compile-time immediate offsets from one base (pad-and-shift:
//       s == w (mod 2) => (w-s)/2 = b - si with b = w>>1; borders are zero pads).
//  Writes every output element (poison-safe).
// ---------------------------------------------------------------------------
#define FW 132                        // padded row width: [0..3]=0, data 4..128, [129..131]=0
__global__ __launch_bounds__(256) void fold_kernel(float* __restrict__ out) {
    const int c   = blockIdx.x >> 8;
    const int h   = blockIdx.x & 255;
    const int par = h & 1;

    __shared__ float s_rows[28][FW];

    const int lane = threadIdx.x & 31;
    const int wrp  = threadIdx.x >> 5;

    // staging: row rr = wrp + 8k (k=0..3; rr<28)
#pragma unroll
    for (int k = 0; k < 4; k++) {
        const int rr = wrp + 8 * k;
        if (rr >= 28) break;                      // warp-uniform
        const int ridx = rr / 7;                  // warp-uniform (compiler: k,wrp known / cheap)
        const int s    = rr - ridx * 7;
        const int r    = par + 2 * ridx;
        const int i2   = h - r;
        const bool ok  = (r <= 6) && (i2 >= 0) && (i2 <= 2 * (NN - 1));
        float* dst = &s_rows[rr][0];
        if (ok) {
            const float* src = g_ZT + ((c * 7 + r) * 7 + s) * NQS + (i2 >> 1) * NN;
#pragma unroll
            for (int t = 0; t < 4; t++) {
                const int j = t * 32 + lane;
                if (j < 125) dst[4 + j] = src[j];
            }
        } else {
#pragma unroll
            for (int t = 0; t < 4; t++) {
                const int j = t * 32 + lane;
                if (j < 125) dst[4 + j] = 0.f;
            }
        }
        if (lane < 4) dst[lane] = 0.f;            // left pad
        if (lane < 3) dst[129 + lane] = 0.f;      // right pad
    }
    __syncthreads();

    // sum: 16 immediate-offset LDS from base b = w>>1
    const int w    = threadIdx.x;
    const int wpar = w & 1;
    const int b    = w >> 1;
    float acc = 0.f;
    if (wpar == 0) {
#pragma unroll
        for (int ridx = 0; ridx < 4; ridx++)
#pragma unroll
            for (int si = 0; si < 4; si++)        // s = 2*si : 0,2,4,6
                acc += s_rows[ridx * 7 + 2 * si][4 + b - si];
    } else {
#pragma unroll
        for (int ridx = 0; ridx < 4; ridx++)
#pragma unroll
            for (int si = 0; si < 3; si++)        // s = 1+2*si : 1,3,5
                acc += s_rows[ridx * 7 + 1 + 2 * si][4 + b - si];
    }
    out[blockIdx.x * 256 + w] = acc;
}

// ---------------------------------------------------------------------------
extern "C" void kernel_launch(void* const* d_in, const int* in_sizes, int n_in,
                              void* d_out, int out_size) {
    const float* x    = (const float*)d_in[0];
    const float* xe   = (const float*)d_in[1];
    const float* ye   = (const float*)d_in[2];
    const int*   inds = (const int*)  d_in[3];
    float*       out  = (float*)d_out;
    (void)in_sizes; (void)n_in; (void)out_size;

    agg_kernel<<<(NQ + 7) / 8, 256>>>(x, xe, ye, inds);
    fold_kernel<<<CC * HH, 256>>>(out);
}